// round 5
// baseline (speedup 1.0000x reference)
#include <cuda_runtime.h>
#include <math.h>
#include <stdint.h>

// ---------------- problem constants ----------------
#define NTOT   (1024 * 32)   // B*T = 32768
#define DIMIN  640
#define HID    512
#define ODIM   288
#define NJ     24
// split offsets in the 288-dim MLP output:
// pos_delta[0:3) rot_delta[3:6) dof_delta[6:75) lin_vel[75:147) ang_vel[147:219) dof_vel[219:288)

// ---------------- scratch (no allocations allowed; referenced directly) ---------
__device__ float g_bufA[(size_t)NTOT * HID];   // h0, then reused for h2
__device__ float g_bufB[(size_t)NTOT * HID];   // h1
__device__ float g_mlp [(size_t)NTOT * ODIM];  // final MLP output

__constant__ int c_parents[NJ] = {-1,0,0,0,1,2,3,4,5,6,7,8,9,9,9,12,13,14,16,17,18,19,20,21};

// Scratch-buffer selector so kernels never take raw scratch pointers from host.
// 0 = g_bufA, 1 = g_bufB, 2 = g_mlp, 3 = external (use provided pointer)
template <int SEL>
__device__ __forceinline__ float* scratch_ptr(float* ext) {
    if (SEL == 0) return g_bufA;
    if (SEL == 1) return g_bufB;
    if (SEL == 2) return g_mlp;
    return ext;
}

// ---------------- fp32 tiled GEMM:  Y[n,o] = act( sum_k X[n,k]*W[o,k] + b[o] ) -----
// BM=128, BN=64, BK=16, 256 threads, 8x4 microtile per thread.
// SRC/DST select device-global scratch; SRC==3 reads the external X pointer.
template <bool SILU, int SRC, int DST>
__global__ __launch_bounds__(256) void gemm_bias_act(
    const float* __restrict__ Xext, const float* __restrict__ W,
    const float* __restrict__ bias, int K, int O)
{
    const float* X = (SRC == 3) ? Xext : (const float*)scratch_ptr<SRC>(nullptr);
    float*       Y = scratch_ptr<DST>(nullptr);

    __shared__ float Xs[16][132];   // padded to reduce bank conflicts
    __shared__ float Ws[16][68];

    const int tid = threadIdx.x;
    const int bm  = blockIdx.y * 128;
    const int bn  = blockIdx.x * 64;
    const int tx  = tid & 15;   // 16 column groups (4 cols each)
    const int ty  = tid >> 4;   // 16 row groups   (8 rows each)

    float acc[8][4];
#pragma unroll
    for (int i = 0; i < 8; i++)
#pragma unroll
        for (int j = 0; j < 4; j++) acc[i][j] = 0.0f;

    for (int k0 = 0; k0 < K; k0 += 16) {
        // ---- load X tile (128 x 16) : 512 float4, 2 per thread ----
#pragma unroll
        for (int l = 0; l < 2; l++) {
            int c   = tid + l * 256;
            int row = c >> 2;
            int kq  = c & 3;
            float4 v = *reinterpret_cast<const float4*>(
                &X[(size_t)(bm + row) * K + k0 + kq * 4]);
            Xs[kq * 4 + 0][row] = v.x;
            Xs[kq * 4 + 1][row] = v.y;
            Xs[kq * 4 + 2][row] = v.z;
            Xs[kq * 4 + 3][row] = v.w;
        }
        // ---- load W tile (64 x 16) : 256 float4, 1 per thread ----
        {
            int c    = tid;
            int orow = c >> 2;
            int kq   = c & 3;
            float4 v = make_float4(0.f, 0.f, 0.f, 0.f);
            if (bn + orow < O)
                v = *reinterpret_cast<const float4*>(
                    &W[(size_t)(bn + orow) * K + k0 + kq * 4]);
            Ws[kq * 4 + 0][orow] = v.x;
            Ws[kq * 4 + 1][orow] = v.y;
            Ws[kq * 4 + 2][orow] = v.z;
            Ws[kq * 4 + 3][orow] = v.w;
        }
        __syncthreads();

#pragma unroll
        for (int kk = 0; kk < 16; kk++) {
            float a[8], b[4];
#pragma unroll
            for (int i = 0; i < 8; i++) a[i] = Xs[kk][ty * 8 + i];
#pragma unroll
            for (int j = 0; j < 4; j++) b[j] = Ws[kk][tx * 4 + j];
#pragma unroll
            for (int i = 0; i < 8; i++)
#pragma unroll
                for (int j = 0; j < 4; j++)
                    acc[i][j] = fmaf(a[i], b[j], acc[i][j]);
        }
        __syncthreads();
    }

#pragma unroll
    for (int i = 0; i < 8; i++) {
        int row = bm + ty * 8 + i;
#pragma unroll
        for (int j = 0; j < 4; j++) {
            int col = bn + tx * 4 + j;
            if (col < O) {
                float y = acc[i][j] + bias[col];
                if (SILU) y = y / (1.0f + expf(-y));
                Y[(size_t)row * O + col] = y;
            }
        }
    }
}

// ---------------- quaternion helpers (match reference math exactly) -------------
struct Qt { float x, y, z, w; };
struct V3 { float x, y, z; };

__device__ __forceinline__ Qt qmul(Qt a, Qt b) {
    Qt r;
    r.x = a.w * b.x + a.x * b.w + a.y * b.z - a.z * b.y;
    r.y = a.w * b.y + a.y * b.w + a.z * b.x - a.x * b.z;
    r.z = a.w * b.z + a.z * b.w + a.x * b.y - a.y * b.x;
    r.w = a.w * b.w - a.x * b.x - a.y * b.y - a.z * b.z;
    return r;
}

__device__ __forceinline__ V3 qrot(Qt q, V3 v) {
    float tw = 2.0f * q.w;
    float s  = tw * q.w - 1.0f;                       // (2w^2 - 1)
    float d  = 2.0f * (q.x * v.x + q.y * v.y + q.z * v.z);
    V3 r;
    r.x = v.x * s + (q.y * v.z - q.z * v.y) * tw + q.x * d;
    r.y = v.y * s + (q.z * v.x - q.x * v.z) * tw + q.y * d;
    r.z = v.z * s + (q.x * v.y - q.y * v.x) * tw + q.z * d;
    return r;
}

__device__ __forceinline__ float norm_angle(float x) {
    return atan2f(sinf(x), cosf(x));
}

__device__ __forceinline__ Qt exp_to_quat(float x, float y, float z) {
    float angle = sqrtf(x * x + y * y + z * z);
    float ax, ay, az, ang;
    if (angle > 1e-5f) {
        float inv = 1.0f / angle;
        ax = x * inv; ay = y * inv; az = z * inv;
        ang = norm_angle(angle);
    } else {
        ax = 0.0f; ay = 0.0f; az = 1.0f; ang = 0.0f;
    }
    float s = sinf(0.5f * ang), c = cosf(0.5f * ang);
    Qt r; r.x = ax * s; r.y = ay * s; r.z = az * s; r.w = c;
    return r;
}

__device__ __forceinline__ V3 quat_to_exp(Qt q) {
    float qw = fminf(fmaxf(q.w, -1.0f + 1e-7f), 1.0f - 1e-7f);
    float st = sqrtf(1.0f - qw * qw);
    V3 r;
    if (st > 1e-5f) {
        float angle = norm_angle(2.0f * acosf(qw));
        float inv = angle / st;
        r.x = q.x * inv; r.y = q.y * inv; r.z = q.z * inv;
    } else {
        r.x = 0.0f; r.y = 0.0f; r.z = 0.0f;  // angle=0 => 0*axis
    }
    return r;
}

// ---------------- post-processing: 1 thread per sample --------------------------
__global__ __launch_bounds__(256) void post_kernel(
    const float* __restrict__ rg_pos,
    const float* __restrict__ rg_rot,
    const float* __restrict__ dof_pos,
    const float* __restrict__ ltr,      // local_trans [24,3]
    float* __restrict__ out, int N)
{
    int n = blockIdx.x * blockDim.x + threadIdx.x;
    if (n >= N) return;

    const float* o = g_mlp + (size_t)n * ODIM;

    float* bp = out;                         // body_pos  [N,24,3]
    float* bq = out + (size_t)N * 72;        // body_quat [N,24,4]
    float* dp = out + (size_t)N * 168;       // dof_pos   [N,23,3]
    float* lv = out + (size_t)N * 237;       // lin_vel   [N,24,3]
    float* av = out + (size_t)N * 309;       // ang_vel   [N,24,3]
    float* dv = out + (size_t)N * 381;       // dof_vel   [N,23,3]

    // root state
    V3 root_pos; root_pos.x = rg_pos[(size_t)n * 72 + 0];
    root_pos.y = rg_pos[(size_t)n * 72 + 1];
    root_pos.z = rg_pos[(size_t)n * 72 + 2];
    Qt root_rot; root_rot.x = rg_rot[(size_t)n * 96 + 0];
    root_rot.y = rg_rot[(size_t)n * 96 + 1];
    root_rot.z = rg_rot[(size_t)n * 96 + 2];
    root_rot.w = rg_rot[(size_t)n * 96 + 3];

    // heading quaternion
    V3 ref; ref.x = 1.0f; ref.y = 0.0f; ref.z = 0.0f;
    V3 rd = qrot(root_rot, ref);
    float h  = atan2f(rd.y, rd.x);
    float sh = sinf(0.5f * h), ch = cosf(0.5f * h);
    Qt hq;   hq.x = 0.f;  hq.y = 0.f;  hq.z = sh;   hq.w = ch;
    Qt hinv; hinv.x = 0.f; hinv.y = 0.f; hinv.z = -sh; hinv.w = ch;

    // new root position
    V3 pd; pd.x = o[0]; pd.y = o[1]; pd.z = o[2];
    V3 rp = qrot(hq, pd);
    V3 nrp; nrp.x = root_pos.x + rp.x; nrp.y = root_pos.y + rp.y; nrp.z = root_pos.z + rp.z;

    // new root rotation
    Qt rdl = exp_to_quat(o[3], o[4], o[5]);
    Qt rq  = qmul(qmul(hq, rdl), hinv);
    Qt nrr = qmul(rq, root_rot);

    // FK: keep world pos/rot in registers/local (24 joints)
    V3 wp[NJ];
    Qt wr[NJ];
    wp[0] = nrp;
    wr[0] = nrr;

    size_t pb = (size_t)n * 72;
    size_t qb = (size_t)n * 96;

    for (int i = 1; i < NJ; i++) {
        int j = i - 1;
        Qt cur = exp_to_quat(dof_pos[(size_t)n * 69 + 3 * j + 0],
                             dof_pos[(size_t)n * 69 + 3 * j + 1],
                             dof_pos[(size_t)n * 69 + 3 * j + 2]);
        Qt del = exp_to_quat(o[6 + 3 * j + 0], o[6 + 3 * j + 1], o[6 + 3 * j + 2]);
        Qt dq  = qmul(del, cur);

        V3 e = quat_to_exp(dq);
        dp[(size_t)n * 69 + 3 * j + 0] = e.x;
        dp[(size_t)n * 69 + 3 * j + 1] = e.y;
        dp[(size_t)n * 69 + 3 * j + 2] = e.z;

        int p = c_parents[i];
        V3 lt; lt.x = ltr[3 * i + 0]; lt.y = ltr[3 * i + 1]; lt.z = ltr[3 * i + 2];
        V3 jr = qrot(wr[p], lt);
        wp[i].x = jr.x + wp[p].x; wp[i].y = jr.y + wp[p].y; wp[i].z = jr.z + wp[p].z;
        wr[i] = qmul(wr[p], dq);
    }

#pragma unroll
    for (int i = 0; i < NJ; i++) {
        bp[pb + 3 * i + 0] = wp[i].x;
        bp[pb + 3 * i + 1] = wp[i].y;
        bp[pb + 3 * i + 2] = wp[i].z;
        bq[qb + 4 * i + 0] = wr[i].x;
        bq[qb + 4 * i + 1] = wr[i].y;
        bq[qb + 4 * i + 2] = wr[i].z;
        bq[qb + 4 * i + 3] = wr[i].w;
    }

    // velocities rotated into heading frame
#pragma unroll
    for (int i = 0; i < NJ; i++) {
        V3 v; v.x = o[75 + 3 * i + 0]; v.y = o[75 + 3 * i + 1]; v.z = o[75 + 3 * i + 2];
        V3 rv = qrot(hq, v);
        lv[(size_t)n * 72 + 3 * i + 0] = rv.x;
        lv[(size_t)n * 72 + 3 * i + 1] = rv.y;
        lv[(size_t)n * 72 + 3 * i + 2] = rv.z;

        V3 w; w.x = o[147 + 3 * i + 0]; w.y = o[147 + 3 * i + 1]; w.z = o[147 + 3 * i + 2];
        V3 rw2 = qrot(hq, w);
        av[(size_t)n * 72 + 3 * i + 0] = rw2.x;
        av[(size_t)n * 72 + 3 * i + 1] = rw2.y;
        av[(size_t)n * 72 + 3 * i + 2] = rw2.z;
    }

    // dof_vel passthrough
#pragma unroll
    for (int k = 0; k < 69; k++)
        dv[(size_t)n * 69 + k] = o[219 + k];
}

// ---------------- launch ---------------------------------------------------------
extern "C" void kernel_launch(void* const* d_in, const int* in_sizes, int n_in,
                              void* d_out, int out_size)
{
    (void)n_in; (void)out_size;
    const float* x_in   = (const float*)d_in[0];   // self_obs_and_action [N,640]
    const float* rg_pos = (const float*)d_in[1];   // [N,72]
    const float* rg_rot = (const float*)d_in[2];   // [N,96]
    // d_in[3] rg_vel, d_in[4] rg_ang_vel : unused by reference
    const float* dofp   = (const float*)d_in[5];   // [N,69]
    const float* W0 = (const float*)d_in[6];
    const float* b0 = (const float*)d_in[7];
    const float* W1 = (const float*)d_in[8];
    const float* b1 = (const float*)d_in[9];
    const float* W2 = (const float*)d_in[10];
    const float* b2 = (const float*)d_in[11];
    const float* W3 = (const float*)d_in[12];
    const float* b3 = (const float*)d_in[13];
    const float* lt = (const float*)d_in[14];      // [24,3]

    const int N = in_sizes[1] / 72;                // 32768

    dim3 blk(256);
    dim3 g0((HID + 63) / 64, N / 128);
    dim3 g3((ODIM + 63) / 64, N / 128);

    // SRC/DST: 0=g_bufA, 1=g_bufB, 2=g_mlp, 3=external
    gemm_bias_act<true , 3, 0><<<g0, blk>>>(x_in,    W0, b0, DIMIN, HID);
    gemm_bias_act<true , 0, 1><<<g0, blk>>>(nullptr, W1, b1, HID,   HID);
    gemm_bias_act<true , 1, 0><<<g0, blk>>>(nullptr, W2, b2, HID,   HID);
    gemm_bias_act<false, 0, 2><<<g3, blk>>>(nullptr, W3, b3, HID,   ODIM);

    post_kernel<<<(N + 255) / 256, 256>>>(rg_pos, rg_rot, dofp, lt,
                                          (float*)d_out, N);
}